// round 6
// baseline (speedup 1.0000x reference)
#include <cuda_runtime.h>
#include <stdint.h>

// PHM embedding: out[tok, q*256 + j] = sum_k a[k,p,q] * s[k,i,j]
//   t = input[tok]; p = t / 12565; i = t % 12565
//   a: [4,4,4] (k,p,q) f32 ; s: [4,12565,256] f32 ; out: [16384,1024] f32
//
// L2-residency play: s loads use ld.global.nc.L2::evict_last (requires
// .v8.b32 => 32B/lane => 32 lanes per token), output stores use
// st.global.cs (evict-first). s (51.5MB) then stays pinned in the 126MB L2
// across graph replays; DRAM carries only the write stream.

static constexpr int N_ROWS = 12565;          // VOCAB_PAD / 4
static constexpr int ROW_F  = 256;            // floats per s row
static constexpr int PLANE  = N_ROWS * ROW_F; // k-plane stride in floats
static constexpr int TOK_PER_BLK = 8;         // 8 tokens x 32 lanes = 256 thr

__device__ __forceinline__ void ldg_el32(const float* p, float* v) {
    uint32_t r0,r1,r2,r3,r4,r5,r6,r7;
    asm volatile("ld.global.nc.L2::evict_last.v8.b32 {%0,%1,%2,%3,%4,%5,%6,%7}, [%8];"
                 : "=r"(r0),"=r"(r1),"=r"(r2),"=r"(r3),
                   "=r"(r4),"=r"(r5),"=r"(r6),"=r"(r7)
                 : "l"(p));
    v[0]=__uint_as_float(r0); v[1]=__uint_as_float(r1);
    v[2]=__uint_as_float(r2); v[3]=__uint_as_float(r3);
    v[4]=__uint_as_float(r4); v[5]=__uint_as_float(r5);
    v[6]=__uint_as_float(r6); v[7]=__uint_as_float(r7);
}

__device__ __forceinline__ void stg_cs16(float* p, float a, float b, float c, float d) {
    asm volatile("st.global.cs.v4.f32 [%0], {%1,%2,%3,%4};"
                 :: "l"(p), "f"(a), "f"(b), "f"(c), "f"(d)
                 : "memory");
}

__global__ void __launch_bounds__(256, 4)
phm_embed_kernel(const int* __restrict__ inp,
                 const float* __restrict__ a,
                 const float* __restrict__ s,
                 float* __restrict__ out,
                 int n_tok)
{
    const int lane = threadIdx.x & 31;        // 32B chunk within row
    const int tsub = threadIdx.x >> 5;        // token within block (0..7)
    const int tok  = blockIdx.x * TOK_PER_BLK + tsub;
    if (tok >= n_tok) return;

    const int t = inp[tok];
    const int p = t / N_ROWS;                 // compile-time magic divide
    const int i = t - p * N_ROWS;

    const float* srow = s + (size_t)i * ROW_F + lane * 8;

    // 4 independent 32B evict_last loads (one per k-plane), front-batched.
    float sv0[8], sv1[8], sv2[8], sv3[8];
    ldg_el32(srow + 0 * PLANE, sv0);
    ldg_el32(srow + 1 * PLANE, sv1);
    ldg_el32(srow + 2 * PLANE, sv2);
    ldg_el32(srow + 3 * PLANE, sv3);

    // a[k,p,q] = a[k*16 + p*4 + q]; broadcast loads, L1-resident.
    const float* ap = a + p * 4;

    float* outp = out + (size_t)tok * 1024 + lane * 8;

#pragma unroll
    for (int q = 0; q < 4; q++) {
        const float c0 = __ldg(&ap[ 0 + q]);
        const float c1 = __ldg(&ap[16 + q]);
        const float c2 = __ldg(&ap[32 + q]);
        const float c3 = __ldg(&ap[48 + q]);

        float o[8];
#pragma unroll
        for (int e = 0; e < 8; e++)
            o[e] = c0 * sv0[e] + c1 * sv1[e] + c2 * sv2[e] + c3 * sv3[e];

        float* dst = outp + q * ROW_F;
        stg_cs16(dst,     o[0], o[1], o[2], o[3]);
        stg_cs16(dst + 4, o[4], o[5], o[6], o[7]);
    }
}

extern "C" void kernel_launch(void* const* d_in, const int* in_sizes, int n_in,
                              void* d_out, int out_size)
{
    const int*   inp = (const int*)d_in[0];    // [8,2048] int32
    const float* a   = (const float*)d_in[1];  // [4,4,4]
    const float* s   = (const float*)d_in[2];  // [4,12565,256]
    float*       out = (float*)d_out;

    const int n_tok = in_sizes[0];              // 16384
    const int grid  = (n_tok + TOK_PER_BLK - 1) / TOK_PER_BLK;
    phm_embed_kernel<<<grid, 256>>>(inp, a, s, out, n_tok);
}

// round 7
// speedup vs baseline: 1.0055x; 1.0055x over previous
#include <cuda_runtime.h>
#include <stdint.h>

// PHM embedding, inverted: iterate over s rows (i) sequentially, scatter to
// tokens. out[tok, q*256+j] = sum_k a[k,p,q] * s[k,i,j], p=t/12565, i=t%12565.
//   a: [4,4,4] f32 ; s: [4,12565,256] f32 ; out: [16384,1024] f32
//
// 3 kernels: zero counts -> histogram tokens into per-i buckets -> stream s
// row-major (skip empty rows), scatter token outputs. Reads each needed s row
// exactly once (~37.5MB vs 51.5MB) and sequentially (streaming BW).

static constexpr int N_ROWS = 12565;   // VOCAB_PAD / 4
static constexpr int EV4    = 64;      // 256 f32 per row = 64 float4
static constexpr int SLOTS  = 32;      // max tokens per i-bucket (P(ovf)~1e-30)
static constexpr int ROWS_PER_BLK = 4; // 4 i-rows x 64 lanes = 256 threads

__device__ int d_count[N_ROWS];
__device__ int d_slots[N_ROWS * SLOTS];

__global__ void zero_counts()
{
    const int idx = blockIdx.x * blockDim.x + threadIdx.x;
    if (idx < N_ROWS) d_count[idx] = 0;
}

__global__ void build_buckets(const int* __restrict__ inp, int n_tok)
{
    const int tok = blockIdx.x * blockDim.x + threadIdx.x;
    if (tok >= n_tok) return;
    const int t = inp[tok];
    const int p = t / N_ROWS;            // magic-number divide
    const int i = t - p * N_ROWS;
    const int r = atomicAdd(&d_count[i], 1);
    if (r < SLOTS) d_slots[i * SLOTS + r] = tok | (p << 14);  // tok<16384
}

__global__ void __launch_bounds__(256)
phm_scatter(const float* __restrict__ a,
            const float4* __restrict__ s,
            float4* __restrict__ out)
{
    const int lane = threadIdx.x & 63;                  // float4 within row
    const int rsub = threadIdx.x >> 6;                  // row within block
    const int i    = blockIdx.x * ROWS_PER_BLK + rsub;
    if (i >= N_ROWS) return;

    const int cnt = d_count[i];
    if (cnt == 0) return;                               // skip untouched rows

    // Stream-load the 4 k-plane rows for this i (sequential across blocks).
    const float4* srow = s + (size_t)i * EV4 + lane;
    const float4 sv0 = __ldg(srow + 0 * N_ROWS * EV4);
    const float4 sv1 = __ldg(srow + 1 * N_ROWS * EV4);
    const float4 sv2 = __ldg(srow + 2 * N_ROWS * EV4);
    const float4 sv3 = __ldg(srow + 3 * N_ROWS * EV4);

    const int* bucket = d_slots + i * SLOTS;

    for (int c = 0; c < cnt; c++) {
        const int v   = bucket[c];
        const int tok = v & 0x3FFF;
        const int p   = v >> 14;

        const float* ap = a + p * 4;                    // a[k,p,q]=a[k*16+p*4+q]
        float4* outp = out + (size_t)tok * 256 + lane;

#pragma unroll
        for (int q = 0; q < 4; q++) {
            const float c0 = __ldg(&ap[ 0 + q]);
            const float c1 = __ldg(&ap[16 + q]);
            const float c2 = __ldg(&ap[32 + q]);
            const float c3 = __ldg(&ap[48 + q]);
            float4 o;
            o.x = c0 * sv0.x + c1 * sv1.x + c2 * sv2.x + c3 * sv3.x;
            o.y = c0 * sv0.y + c1 * sv1.y + c2 * sv2.y + c3 * sv3.y;
            o.z = c0 * sv0.z + c1 * sv1.z + c2 * sv2.z + c3 * sv3.z;
            o.w = c0 * sv0.w + c1 * sv1.w + c2 * sv2.w + c3 * sv3.w;
            outp[q * EV4] = o;
        }
    }
}

extern "C" void kernel_launch(void* const* d_in, const int* in_sizes, int n_in,
                              void* d_out, int out_size)
{
    const int*    inp = (const int*)d_in[0];    // [8,2048] int32
    const float*  a   = (const float*)d_in[1];  // [4,4,4]
    const float4* s   = (const float4*)d_in[2]; // [4,12565,256] as float4
    float4*       out = (float4*)d_out;

    const int n_tok = in_sizes[0];              // 16384

    zero_counts<<<(N_ROWS + 255) / 256, 256>>>();
    build_buckets<<<(n_tok + 255) / 256, 256>>>(inp, n_tok);
    phm_scatter<<<(N_ROWS + ROWS_PER_BLK - 1) / ROWS_PER_BLK, 256>>>(a, s, out);
}